// round 10
// baseline (speedup 1.0000x reference)
#include <cuda_runtime.h>
#include <cuda_bf16.h>
#include <math.h>
#include <stdint.h>

#define BB 4096
#define DD 512
#define QQ 16384
#define UU 256
#define OIM_SCALE 30.0f
#define C_LOG2E 43.280851226668896f   // 30 * log2(e)

// ---------------- scratch (device globals; no allocation allowed) ----------
__device__ float g_cls_sum[UU * DD];              // zeroed by k_gemm prologue
__device__ int   g_cls_cnt[UU];                   // zeroed by k_gemm prologue
__device__ int   g_unrank[UU];
__device__ float g_uniq_emb_n[UU * DD];
__device__ __nv_bfloat16 g_Abf[BB * DD];          // 4 MB (normalized inputs, bf16)
__device__ __nv_bfloat16 g_Bbf[(size_t)QQ * DD];  // 16 MB (effective queue, bf16)
__device__ unsigned char g_good[QQ];
__device__ float g_target[BB];
__device__ float g_rowsum[BB];
__device__ unsigned int g_ticket;                 // arrival counter (self-resetting)

// ---------------- helpers ----------------------------------------------------
__device__ __forceinline__ uint32_t smem_u32(const void* p) {
    uint32_t a;
    asm("{ .reg .u64 t; cvta.to.shared.u64 t, %1; cvt.u32.u64 %0, t; }"
        : "=r"(a) : "l"(p));
    return a;
}
__device__ __forceinline__ void cpa16(uint32_t sm, const void* g) {
    asm volatile("cp.async.cg.shared.global [%0], [%1], 16;" :: "r"(sm), "l"(g));
}
__device__ __forceinline__ void cpa_commit() {
    asm volatile("cp.async.commit_group;" ::: "memory");
}
__device__ __forceinline__ void ldsm4(uint32_t* r, uint32_t addr) {
    asm volatile("ldmatrix.sync.aligned.m8n8.x4.shared.b16 {%0,%1,%2,%3}, [%4];"
                 : "=r"(r[0]), "=r"(r[1]), "=r"(r[2]), "=r"(r[3]) : "r"(addr));
}
__device__ __forceinline__ void mma16816(float* d, const uint32_t* a,
                                         const uint32_t* b) {
    asm volatile(
        "mma.sync.aligned.m16n8k16.row.col.f32.bf16.bf16.f32 "
        "{%0,%1,%2,%3}, {%4,%5,%6,%7}, {%8,%9}, {%0,%1,%2,%3};"
        : "+f"(d[0]), "+f"(d[1]), "+f"(d[2]), "+f"(d[3])
        : "r"(a[0]), "r"(a[1]), "r"(a[2]), "r"(a[3]), "r"(b[0]), "r"(b[1]));
}
#define SWZ(o) ((o) ^ (((o) >> 3) & 0x70))

__device__ __forceinline__ void pack_bf16_store(float4 v, __nv_bfloat16* dst,
                                                size_t e) {
    __nv_bfloat162 h01 = __floats2bfloat162_rn(v.x, v.y);
    __nv_bfloat162 h23 = __floats2bfloat162_rn(v.z, v.w);
    uint2 u;
    u.x = *reinterpret_cast<uint32_t*>(&h01);
    u.y = *reinterpret_cast<uint32_t*>(&h23);
    reinterpret_cast<uint2*>(dst)[e >> 2] = u;
}

// ---------------- 1: normalize rows -> bf16 A + scatter (2 rows/block) ------
__global__ void k_row(const float* __restrict__ inputs,
                      const int*   __restrict__ labels) {
    int b0 = blockIdx.x * 2;      // 2048 blocks
    int t = threadIdx.x;          // 128
    const float4 v0 = reinterpret_cast<const float4*>(inputs + (size_t)b0 * DD)[t];
    const float4 v1 = reinterpret_cast<const float4*>(inputs + (size_t)(b0 + 1) * DD)[t];
    float s0 = v0.x * v0.x + v0.y * v0.y + v0.z * v0.z + v0.w * v0.w;
    float s1 = v1.x * v1.x + v1.y * v1.y + v1.z * v1.z + v1.w * v1.w;
    #pragma unroll
    for (int o = 16; o; o >>= 1) {
        s0 += __shfl_xor_sync(0xffffffffu, s0, o);
        s1 += __shfl_xor_sync(0xffffffffu, s1, o);
    }
    __shared__ float sh[2][4];
    if ((t & 31) == 0) { sh[0][t >> 5] = s0; sh[1][t >> 5] = s1; }
    __syncthreads();
    float inv0 = 1.0f / fmaxf(sqrtf(sh[0][0] + sh[0][1] + sh[0][2] + sh[0][3]), 1e-12f);
    float inv1 = 1.0f / fmaxf(sqrtf(sh[1][0] + sh[1][1] + sh[1][2] + sh[1][3]), 1e-12f);
    pack_bf16_store(make_float4(v0.x * inv0, v0.y * inv0, v0.z * inv0, v0.w * inv0),
                    g_Abf, (size_t)b0 * DD + t * 4);
    pack_bf16_store(make_float4(v1.x * inv1, v1.y * inv1, v1.z * inv1, v1.w * inv1),
                    g_Abf, (size_t)(b0 + 1) * DD + t * 4);

    int lab0 = labels[b0], lab1 = labels[b0 + 1];
    float* c0 = g_cls_sum + lab0 * DD + t * 4;
    float* c1 = g_cls_sum + lab1 * DD + t * 4;
    atomicAdd(c0 + 0, v0.x); atomicAdd(c0 + 1, v0.y);
    atomicAdd(c0 + 2, v0.z); atomicAdd(c0 + 3, v0.w);
    atomicAdd(c1 + 0, v1.x); atomicAdd(c1 + 1, v1.y);
    atomicAdd(c1 + 2, v1.z); atomicAdd(c1 + 3, v1.w);
    if (t == 0) { atomicAdd(&g_cls_cnt[lab0], 1); atomicAdd(&g_cls_cnt[lab1], 1); }
}

// ---------------- 2: class means, normalized + rank table --------------------
__global__ void k_class() {
    int u = blockIdx.x;           // 256 blocks
    int t = threadIdx.x;          // 128
    int cnt = g_cls_cnt[u];
    float invc = cnt > 0 ? 1.0f / (float)cnt : 0.0f;
    float4 v = reinterpret_cast<const float4*>(g_cls_sum + u * DD)[t];
    v.x *= invc; v.y *= invc; v.z *= invc; v.w *= invc;
    float ss = v.x * v.x + v.y * v.y + v.z * v.z + v.w * v.w;
    #pragma unroll
    for (int o = 16; o; o >>= 1) ss += __shfl_xor_sync(0xffffffffu, ss, o);
    __shared__ float sh[4];
    __shared__ int shr[4];
    int rloc = 0;
    if (t < u && g_cls_cnt[t] > 0) rloc++;
    if (t + 128 < u && g_cls_cnt[t + 128] > 0) rloc++;
    #pragma unroll
    for (int o = 16; o; o >>= 1) rloc += __shfl_xor_sync(0xffffffffu, rloc, o);
    if ((t & 31) == 0) { sh[t >> 5] = ss; shr[t >> 5] = rloc; }
    __syncthreads();
    float inv = 1.0f / fmaxf(sqrtf(sh[0] + sh[1] + sh[2] + sh[3]), 1e-12f);
    float4 vn = make_float4(v.x * inv, v.y * inv, v.z * inv, v.w * inv);
    reinterpret_cast<float4*>(g_uniq_emb_n + u * DD)[t] = vn;
    if (t == 0 && cnt > 0) {
        int r = shr[0] + shr[1] + shr[2] + shr[3];
        g_unrank[r] = u;
    }
}

// ---------------- 3: fused queue resolution (2 rows, MLP 2) + target logits --
__global__ void k_build(const float* __restrict__ emb_cq,
                        const int*   __restrict__ label_cq,
                        const int*   __restrict__ header,
                        const int*   __restrict__ labels,
                        const float* __restrict__ inputs) {
    int blk = blockIdx.x;
    int t = threadIdx.x;          // 128

    if (blk < QQ / 2) {
        int h0 = header[0];
        int q0 = blk * 2, q1 = q0 + 1;
        // resolve both sources first, then issue both loads (MLP=2)
        const float* src[2];
        unsigned char good[2];
        #pragma unroll
        for (int i = 0; i < 2; i++) {
            int q = q0 + i;
            int u = q - h0;
            u = ((u % QQ) + QQ) % QQ;
            if (u < UU) {
                src[i] = g_uniq_emb_n + g_unrank[u] * DD;
                good[i] = 1;
            } else {
                int lab = label_cq[q];
                bool inuniq = (lab >= 0 && lab < UU && g_cls_cnt[lab] > 0);
                good[i] = (lab != -1 && !inuniq) ? 1 : 0;
                src[i] = emb_cq + (size_t)q * DD;
            }
        }
        float4 v0 = reinterpret_cast<const float4*>(src[0])[t];
        float4 v1 = reinterpret_cast<const float4*>(src[1])[t];
        pack_bf16_store(v0, g_Bbf, (size_t)q0 * DD + t * 4);
        pack_bf16_store(v1, g_Bbf, (size_t)q1 * DD + t * 4);
        if (t == 0) { g_good[q0] = good[0]; g_good[q1] = good[1]; }
    } else {
        int b = blk - QQ / 2;
        int lab = labels[b];
        float4 a = reinterpret_cast<const float4*>(inputs + (size_t)b * DD)[t];
        float4 e = reinterpret_cast<const float4*>(g_uniq_emb_n + lab * DD)[t];
        float ss = a.x * a.x + a.y * a.y + a.z * a.z + a.w * a.w;
        float s  = a.x * e.x + a.y * e.y + a.z * e.z + a.w * e.w;
        #pragma unroll
        for (int o = 16; o; o >>= 1) {
            ss += __shfl_xor_sync(0xffffffffu, ss, o);
            s  += __shfl_xor_sync(0xffffffffu, s, o);
        }
        __shared__ float shs[4], shd[4];
        if ((t & 31) == 0) { shs[t >> 5] = ss; shd[t >> 5] = s; }
        __syncthreads();
        if (t == 0) {
            float tot_ss = shs[0] + shs[1] + shs[2] + shs[3];
            float tot_s  = shd[0] + shd[1] + shd[2] + shd[3];
            float inv = 1.0f / fmaxf(sqrtf(tot_ss), 1e-12f);
            g_target[b] = OIM_SCALE * tot_s * inv;
            g_rowsum[b] = 0.0f;
        }
    }
}

// ---------------- 4: HMMA GEMM + exp row-sum + FUSED final reduce -------------
// R9 config untouched (128x128, 3 stages, 8 warps 4m x 2n, full unroll,
// two barriers per chunk). Last-arriving CTA performs the final loss reduce.
#define STAGES 3
#define STAGE_BYTES 32768           // (128+128) rows * 128B
#define B_OFF 16384
#define GOOD_OFF (STAGES * STAGE_BYTES)
#define SMEM_DYN (GOOD_OFF + 512 + 1024)
#define NCTAS ((QQ / 128) * (BB / 128))

__global__ void __launch_bounds__(256, 2) k_gemm(float* __restrict__ out) {
    extern __shared__ char smraw[];
    const uint32_t sb0 = smem_u32(smraw);
    const uint32_t sbase = (sb0 + 1023) & ~1023u;
    char* smc = smraw + (sbase - sb0);
    float* goodf = (float*)(smc + GOOD_OFF);

    const int tid = threadIdx.x;
    const int lid = tid & 31;
    const int w = tid >> 5;
    const int wm = w >> 1;          // 0..3
    const int wn = w & 1;           // 0..1
    const int n0 = blockIdx.x * 128;
    const int m0 = blockIdx.y * 128;

    // self-cleaning: reset class accumulators for the NEXT graph replay.
    if (blockIdx.y == 0) {
        reinterpret_cast<float4*>(g_cls_sum)[blockIdx.x * 256 + tid] =
            make_float4(0.0f, 0.0f, 0.0f, 0.0f);
        if (blockIdx.x == 0) g_cls_cnt[tid] = 0;
    }

    if (tid < 128) goodf[tid] = (float)g_good[n0 + tid];

    const int lrow = tid >> 3;      // 0..31
    const int lch = tid & 7;
    uint32_t soff[4];
    #pragma unroll
    for (int it = 0; it < 4; it++) {
        uint32_t o = (uint32_t)(lrow + it * 32) * 128 + lch * 16;
        soff[it] = SWZ(o);
    }

    float acc[2][8][4];
    #pragma unroll
    for (int i = 0; i < 2; i++)
        #pragma unroll
        for (int j = 0; j < 8; j++)
            #pragma unroll
            for (int k = 0; k < 4; k++) acc[i][j][k] = 0.0f;

    auto load_stage = [&](int s, int kc) {
        uint32_t sa = sbase + s * STAGE_BYTES;
        const __nv_bfloat16* gA = g_Abf + (size_t)(m0 + lrow) * DD + kc * 64 + lch * 8;
        const __nv_bfloat16* gB = g_Bbf + (size_t)(n0 + lrow) * DD + kc * 64 + lch * 8;
        #pragma unroll
        for (int it = 0; it < 4; it++) {
            cpa16(sa + soff[it], gA + (size_t)it * 32 * DD);
            cpa16(sa + B_OFF + soff[it], gB + (size_t)it * 32 * DD);
        }
        cpa_commit();
    };

    load_stage(0, 0);
    load_stage(1, 1);

    const int arow = wm * 32 + (lid & 15);
    const int acolh = lid >> 4;
    const int brow = wn * 64 + ((lid >> 4) << 3) + (lid & 7);
    const int bcolh = (lid >> 3) & 1;

    #pragma unroll
    for (int c = 0; c < 8; c++) {
        if (c < 7) asm volatile("cp.async.wait_group 1;" ::: "memory");
        else       asm volatile("cp.async.wait_group 0;" ::: "memory");
        __syncthreads();
        if (c + 2 < 8) load_stage((c + 2) % STAGES, c + 2);

        uint32_t sa = sbase + (c % STAGES) * STAGE_BYTES;
        uint32_t sb = sa + B_OFF;
        #pragma unroll
        for (int kk = 0; kk < 4; kk++) {
            uint32_t a[2][4];
            #pragma unroll
            for (int mi = 0; mi < 2; mi++) {
                uint32_t o = (uint32_t)(arow + mi * 16) * 128 +
                             (kk * 2 + acolh) * 16;
                ldsm4(a[mi], sa + SWZ(o));
            }
            uint32_t b[8][2];
            #pragma unroll
            for (int nj = 0; nj < 4; nj++) {
                uint32_t q[4];
                uint32_t o = (uint32_t)(brow + nj * 16) * 128 +
                             (kk * 2 + bcolh) * 16;
                ldsm4(q, sb + SWZ(o));
                b[2 * nj][0] = q[0]; b[2 * nj][1] = q[1];
                b[2 * nj + 1][0] = q[2]; b[2 * nj + 1][1] = q[3];
            }
            #pragma unroll
            for (int mi = 0; mi < 2; mi++)
                #pragma unroll
                for (int ni = 0; ni < 8; ni++)
                    mma16816(acc[mi][ni], a[mi], b[ni]);
        }
        __syncthreads();
    }

    // epilogue: masked exp row-sums (exp2 form: one FFMA + MUFU per element)
    float rs[4] = {0.0f, 0.0f, 0.0f, 0.0f};
    #pragma unroll
    for (int mi = 0; mi < 2; mi++) {
        #pragma unroll
        for (int ni = 0; ni < 8; ni++) {
            int col = wn * 64 + ni * 8 + ((lid & 3) << 1);
            float g0 = goodf[col], g1 = goodf[col + 1];
            float* cacc = acc[mi][ni];
            rs[mi * 2 + 0] += g0 * exp2f(fmaf(C_LOG2E, cacc[0], -C_LOG2E))
                            + g1 * exp2f(fmaf(C_LOG2E, cacc[1], -C_LOG2E));
            rs[mi * 2 + 1] += g0 * exp2f(fmaf(C_LOG2E, cacc[2], -C_LOG2E))
                            + g1 * exp2f(fmaf(C_LOG2E, cacc[3], -C_LOG2E));
        }
    }
    #pragma unroll
    for (int i = 0; i < 4; i++) {
        rs[i] += __shfl_xor_sync(0xffffffffu, rs[i], 1);
        rs[i] += __shfl_xor_sync(0xffffffffu, rs[i], 2);
    }
    if ((lid & 3) == 0) {
        int r0 = m0 + wm * 32 + (lid >> 2);
        atomicAdd(&g_rowsum[r0 +  0], rs[0]);
        atomicAdd(&g_rowsum[r0 +  8], rs[1]);
        atomicAdd(&g_rowsum[r0 + 16], rs[2]);
        atomicAdd(&g_rowsum[r0 + 24], rs[3]);
    }

    // ---- fused final reduce: last CTA to arrive computes the loss ----------
    __threadfence();
    __syncthreads();
    __shared__ unsigned int s_rank;
    if (tid == 0) s_rank = atomicAdd(&g_ticket, 1u);
    __syncthreads();
    if (s_rank == NCTAS - 1) {
        float s = 0.0f;
        for (int b = tid; b < BB; b += 256)
            s += (OIM_SCALE + logf(g_rowsum[b])) - g_target[b];
        #pragma unroll
        for (int o = 16; o; o >>= 1) s += __shfl_xor_sync(0xffffffffu, s, o);
        float* shf = (float*)smc;   // smem free now
        if (lid == 0) shf[w] = s;
        __syncthreads();
        if (tid == 0) {
            float tot = 0.0f;
            #pragma unroll
            for (int i = 0; i < 8; i++) tot += shf[i];
            out[0] = tot / (float)BB;
            g_ticket = 0;           // reset for next graph replay
        }
    }
}

// ---------------- launch ------------------------------------------------------
extern "C" void kernel_launch(void* const* d_in, const int* in_sizes, int n_in,
                              void* d_out, int out_size) {
    const float* inputs   = (const float*)d_in[0];
    const int*   labels   = (const int*)  d_in[1];
    const float* emb_cq   = (const float*)d_in[2];
    const int*   label_cq = (const int*)  d_in[3];
    const int*   header   = (const int*)  d_in[5];
    float* out = (float*)d_out;

    cudaFuncSetAttribute(k_gemm, cudaFuncAttributeMaxDynamicSharedMemorySize,
                         SMEM_DYN);

    k_row<<<BB / 2, 128>>>(inputs, labels);
    k_class<<<UU, 128>>>();
    k_build<<<QQ / 2 + BB, 128>>>(emb_cq, label_cq, header, labels, inputs);
    dim3 grid(QQ / 128, BB / 128);
    k_gemm<<<grid, 256, SMEM_DYN>>>(out);
}

// round 11
// speedup vs baseline: 1.0552x; 1.0552x over previous
#include <cuda_runtime.h>
#include <cuda_bf16.h>
#include <math.h>
#include <stdint.h>

#define BB 4096
#define DD 512
#define QQ 16384
#define UU 256
#define OIM_SCALE 30.0f
#define C_LOG2E 43.280851226668896f   // 30 * log2(e)

// ---------------- scratch (device globals; no allocation allowed) ----------
__device__ float g_cls_sum[UU * DD];              // zeroed by k_gemm prologue
__device__ int   g_cls_cnt[UU];                   // zeroed by k_gemm prologue
__device__ int   g_unrank[UU];
__device__ float g_uniq_emb_n[UU * DD];
__device__ __nv_bfloat16 g_Abf[BB * DD];          // 4 MB (normalized inputs, bf16)
__device__ __nv_bfloat16 g_Bbf[(size_t)QQ * DD];  // 16 MB (effective queue, bf16)
__device__ unsigned char g_good[QQ];
__device__ float g_target[BB];
__device__ float g_rowsum[BB];

// ---------------- helpers ----------------------------------------------------
__device__ __forceinline__ uint32_t smem_u32(const void* p) {
    uint32_t a;
    asm("{ .reg .u64 t; cvta.to.shared.u64 t, %1; cvt.u32.u64 %0, t; }"
        : "=r"(a) : "l"(p));
    return a;
}
__device__ __forceinline__ void cpa16(uint32_t sm, const void* g) {
    asm volatile("cp.async.cg.shared.global [%0], [%1], 16;" :: "r"(sm), "l"(g));
}
__device__ __forceinline__ void cpa_commit() {
    asm volatile("cp.async.commit_group;" ::: "memory");
}
__device__ __forceinline__ void ldsm4(uint32_t* r, uint32_t addr) {
    asm volatile("ldmatrix.sync.aligned.m8n8.x4.shared.b16 {%0,%1,%2,%3}, [%4];"
                 : "=r"(r[0]), "=r"(r[1]), "=r"(r[2]), "=r"(r[3]) : "r"(addr));
}
__device__ __forceinline__ void mma16816(float* d, const uint32_t* a,
                                         const uint32_t* b) {
    asm volatile(
        "mma.sync.aligned.m16n8k16.row.col.f32.bf16.bf16.f32 "
        "{%0,%1,%2,%3}, {%4,%5,%6,%7}, {%8,%9}, {%0,%1,%2,%3};"
        : "+f"(d[0]), "+f"(d[1]), "+f"(d[2]), "+f"(d[3])
        : "r"(a[0]), "r"(a[1]), "r"(a[2]), "r"(a[3]), "r"(b[0]), "r"(b[1]));
}
#define SWZ(o) ((o) ^ (((o) >> 3) & 0x70))

__device__ __forceinline__ void pack_bf16_store(float4 v, __nv_bfloat16* dst,
                                                size_t e) {
    __nv_bfloat162 h01 = __floats2bfloat162_rn(v.x, v.y);
    __nv_bfloat162 h23 = __floats2bfloat162_rn(v.z, v.w);
    uint2 u;
    u.x = *reinterpret_cast<uint32_t*>(&h01);
    u.y = *reinterpret_cast<uint32_t*>(&h23);
    reinterpret_cast<uint2*>(dst)[e >> 2] = u;
}

// ---------------- 1: normalize rows -> bf16 A + scatter (2 rows/block) ------
__global__ void k_row(const float* __restrict__ inputs,
                      const int*   __restrict__ labels) {
    int b0 = blockIdx.x * 2;      // 2048 blocks
    int t = threadIdx.x;          // 128
    const float4 v0 = reinterpret_cast<const float4*>(inputs + (size_t)b0 * DD)[t];
    const float4 v1 = reinterpret_cast<const float4*>(inputs + (size_t)(b0 + 1) * DD)[t];
    float s0 = v0.x * v0.x + v0.y * v0.y + v0.z * v0.z + v0.w * v0.w;
    float s1 = v1.x * v1.x + v1.y * v1.y + v1.z * v1.z + v1.w * v1.w;
    #pragma unroll
    for (int o = 16; o; o >>= 1) {
        s0 += __shfl_xor_sync(0xffffffffu, s0, o);
        s1 += __shfl_xor_sync(0xffffffffu, s1, o);
    }
    __shared__ float sh[2][4];
    if ((t & 31) == 0) { sh[0][t >> 5] = s0; sh[1][t >> 5] = s1; }
    __syncthreads();
    float inv0 = 1.0f / fmaxf(sqrtf(sh[0][0] + sh[0][1] + sh[0][2] + sh[0][3]), 1e-12f);
    float inv1 = 1.0f / fmaxf(sqrtf(sh[1][0] + sh[1][1] + sh[1][2] + sh[1][3]), 1e-12f);
    pack_bf16_store(make_float4(v0.x * inv0, v0.y * inv0, v0.z * inv0, v0.w * inv0),
                    g_Abf, (size_t)b0 * DD + t * 4);
    pack_bf16_store(make_float4(v1.x * inv1, v1.y * inv1, v1.z * inv1, v1.w * inv1),
                    g_Abf, (size_t)(b0 + 1) * DD + t * 4);

    int lab0 = labels[b0], lab1 = labels[b0 + 1];
    float* c0 = g_cls_sum + lab0 * DD + t * 4;
    float* c1 = g_cls_sum + lab1 * DD + t * 4;
    atomicAdd(c0 + 0, v0.x); atomicAdd(c0 + 1, v0.y);
    atomicAdd(c0 + 2, v0.z); atomicAdd(c0 + 3, v0.w);
    atomicAdd(c1 + 0, v1.x); atomicAdd(c1 + 1, v1.y);
    atomicAdd(c1 + 2, v1.z); atomicAdd(c1 + 3, v1.w);
    if (t == 0) { atomicAdd(&g_cls_cnt[lab0], 1); atomicAdd(&g_cls_cnt[lab1], 1); }
}

// ---------------- 2: class means, normalized + rank table --------------------
__global__ void k_class() {
    int u = blockIdx.x;           // 256 blocks
    int t = threadIdx.x;          // 128
    int cnt = g_cls_cnt[u];
    float invc = cnt > 0 ? 1.0f / (float)cnt : 0.0f;
    float4 v = reinterpret_cast<const float4*>(g_cls_sum + u * DD)[t];
    v.x *= invc; v.y *= invc; v.z *= invc; v.w *= invc;
    float ss = v.x * v.x + v.y * v.y + v.z * v.z + v.w * v.w;
    #pragma unroll
    for (int o = 16; o; o >>= 1) ss += __shfl_xor_sync(0xffffffffu, ss, o);
    __shared__ float sh[4];
    __shared__ int shr[4];
    int rloc = 0;
    if (t < u && g_cls_cnt[t] > 0) rloc++;
    if (t + 128 < u && g_cls_cnt[t + 128] > 0) rloc++;
    #pragma unroll
    for (int o = 16; o; o >>= 1) rloc += __shfl_xor_sync(0xffffffffu, rloc, o);
    if ((t & 31) == 0) { sh[t >> 5] = ss; shr[t >> 5] = rloc; }
    __syncthreads();
    float inv = 1.0f / fmaxf(sqrtf(sh[0] + sh[1] + sh[2] + sh[3]), 1e-12f);
    float4 vn = make_float4(v.x * inv, v.y * inv, v.z * inv, v.w * inv);
    reinterpret_cast<float4*>(g_uniq_emb_n + u * DD)[t] = vn;
    if (t == 0 && cnt > 0) {
        int r = shr[0] + shr[1] + shr[2] + shr[3];
        g_unrank[r] = u;
    }
}

// ---------------- 3: fused queue resolution (2 rows, MLP 2) + target logits --
__global__ void k_build(const float* __restrict__ emb_cq,
                        const int*   __restrict__ label_cq,
                        const int*   __restrict__ header,
                        const int*   __restrict__ labels,
                        const float* __restrict__ inputs) {
    int blk = blockIdx.x;
    int t = threadIdx.x;          // 128

    if (blk < QQ / 2) {
        int h0 = header[0];
        int q0 = blk * 2, q1 = q0 + 1;
        const float* src[2];
        unsigned char good[2];
        #pragma unroll
        for (int i = 0; i < 2; i++) {
            int q = q0 + i;
            int u = q - h0;
            u = ((u % QQ) + QQ) % QQ;
            if (u < UU) {
                src[i] = g_uniq_emb_n + g_unrank[u] * DD;
                good[i] = 1;
            } else {
                int lab = label_cq[q];
                bool inuniq = (lab >= 0 && lab < UU && g_cls_cnt[lab] > 0);
                good[i] = (lab != -1 && !inuniq) ? 1 : 0;
                src[i] = emb_cq + (size_t)q * DD;
            }
        }
        float4 v0 = reinterpret_cast<const float4*>(src[0])[t];
        float4 v1 = reinterpret_cast<const float4*>(src[1])[t];
        pack_bf16_store(v0, g_Bbf, (size_t)q0 * DD + t * 4);
        pack_bf16_store(v1, g_Bbf, (size_t)q1 * DD + t * 4);
        if (t == 0) { g_good[q0] = good[0]; g_good[q1] = good[1]; }
    } else {
        int b = blk - QQ / 2;
        int lab = labels[b];
        float4 a = reinterpret_cast<const float4*>(inputs + (size_t)b * DD)[t];
        float4 e = reinterpret_cast<const float4*>(g_uniq_emb_n + lab * DD)[t];
        float ss = a.x * a.x + a.y * a.y + a.z * a.z + a.w * a.w;
        float s  = a.x * e.x + a.y * e.y + a.z * e.z + a.w * e.w;
        #pragma unroll
        for (int o = 16; o; o >>= 1) {
            ss += __shfl_xor_sync(0xffffffffu, ss, o);
            s  += __shfl_xor_sync(0xffffffffu, s, o);
        }
        __shared__ float shs[4], shd[4];
        if ((t & 31) == 0) { shs[t >> 5] = ss; shd[t >> 5] = s; }
        __syncthreads();
        if (t == 0) {
            float tot_ss = shs[0] + shs[1] + shs[2] + shs[3];
            float tot_s  = shd[0] + shd[1] + shd[2] + shd[3];
            float inv = 1.0f / fmaxf(sqrtf(tot_ss), 1e-12f);
            g_target[b] = OIM_SCALE * tot_s * inv;
            g_rowsum[b] = 0.0f;
        }
    }
}

// ---------------- 4: HMMA GEMM + fused masked exp row-sum --------------------
// R9 config, byte-identical mainloop (128x128, 3 stages, 8 warps 4m x 2n,
// full unroll, two barriers per chunk). No fence/ticket in epilogue.
#define STAGES 3
#define STAGE_BYTES 32768           // (128+128) rows * 128B
#define B_OFF 16384
#define GOOD_OFF (STAGES * STAGE_BYTES)
#define SMEM_DYN (GOOD_OFF + 512 + 1024)

__global__ void __launch_bounds__(256, 2) k_gemm() {
    extern __shared__ char smraw[];
    const uint32_t sb0 = smem_u32(smraw);
    const uint32_t sbase = (sb0 + 1023) & ~1023u;
    char* smc = smraw + (sbase - sb0);
    float* goodf = (float*)(smc + GOOD_OFF);

    const int tid = threadIdx.x;
    const int lid = tid & 31;
    const int w = tid >> 5;
    const int wm = w >> 1;          // 0..3
    const int wn = w & 1;           // 0..1
    const int n0 = blockIdx.x * 128;
    const int m0 = blockIdx.y * 128;

    // self-cleaning: reset class accumulators for the NEXT graph replay.
    if (blockIdx.y == 0) {
        reinterpret_cast<float4*>(g_cls_sum)[blockIdx.x * 256 + tid] =
            make_float4(0.0f, 0.0f, 0.0f, 0.0f);
        if (blockIdx.x == 0) g_cls_cnt[tid] = 0;
    }

    if (tid < 128) goodf[tid] = (float)g_good[n0 + tid];

    const int lrow = tid >> 3;      // 0..31
    const int lch = tid & 7;
    uint32_t soff[4];
    #pragma unroll
    for (int it = 0; it < 4; it++) {
        uint32_t o = (uint32_t)(lrow + it * 32) * 128 + lch * 16;
        soff[it] = SWZ(o);
    }

    float acc[2][8][4];
    #pragma unroll
    for (int i = 0; i < 2; i++)
        #pragma unroll
        for (int j = 0; j < 8; j++)
            #pragma unroll
            for (int k = 0; k < 4; k++) acc[i][j][k] = 0.0f;

    auto load_stage = [&](int s, int kc) {
        uint32_t sa = sbase + s * STAGE_BYTES;
        const __nv_bfloat16* gA = g_Abf + (size_t)(m0 + lrow) * DD + kc * 64 + lch * 8;
        const __nv_bfloat16* gB = g_Bbf + (size_t)(n0 + lrow) * DD + kc * 64 + lch * 8;
        #pragma unroll
        for (int it = 0; it < 4; it++) {
            cpa16(sa + soff[it], gA + (size_t)it * 32 * DD);
            cpa16(sa + B_OFF + soff[it], gB + (size_t)it * 32 * DD);
        }
        cpa_commit();
    };

    load_stage(0, 0);
    load_stage(1, 1);

    const int arow = wm * 32 + (lid & 15);
    const int acolh = lid >> 4;
    const int brow = wn * 64 + ((lid >> 4) << 3) + (lid & 7);
    const int bcolh = (lid >> 3) & 1;

    #pragma unroll
    for (int c = 0; c < 8; c++) {
        if (c < 7) asm volatile("cp.async.wait_group 1;" ::: "memory");
        else       asm volatile("cp.async.wait_group 0;" ::: "memory");
        __syncthreads();
        if (c + 2 < 8) load_stage((c + 2) % STAGES, c + 2);

        uint32_t sa = sbase + (c % STAGES) * STAGE_BYTES;
        uint32_t sb = sa + B_OFF;
        #pragma unroll
        for (int kk = 0; kk < 4; kk++) {
            uint32_t a[2][4];
            #pragma unroll
            for (int mi = 0; mi < 2; mi++) {
                uint32_t o = (uint32_t)(arow + mi * 16) * 128 +
                             (kk * 2 + acolh) * 16;
                ldsm4(a[mi], sa + SWZ(o));
            }
            uint32_t b[8][2];
            #pragma unroll
            for (int nj = 0; nj < 4; nj++) {
                uint32_t q[4];
                uint32_t o = (uint32_t)(brow + nj * 16) * 128 +
                             (kk * 2 + bcolh) * 16;
                ldsm4(q, sb + SWZ(o));
                b[2 * nj][0] = q[0]; b[2 * nj][1] = q[1];
                b[2 * nj + 1][0] = q[2]; b[2 * nj + 1][1] = q[3];
            }
            #pragma unroll
            for (int mi = 0; mi < 2; mi++)
                #pragma unroll
                for (int ni = 0; ni < 8; ni++)
                    mma16816(acc[mi][ni], a[mi], b[ni]);
        }
        __syncthreads();
    }

    // epilogue: masked exp row-sums (exp2 form)
    float rs[4] = {0.0f, 0.0f, 0.0f, 0.0f};
    #pragma unroll
    for (int mi = 0; mi < 2; mi++) {
        #pragma unroll
        for (int ni = 0; ni < 8; ni++) {
            int col = wn * 64 + ni * 8 + ((lid & 3) << 1);
            float g0 = goodf[col], g1 = goodf[col + 1];
            float* cacc = acc[mi][ni];
            rs[mi * 2 + 0] += g0 * exp2f(fmaf(C_LOG2E, cacc[0], -C_LOG2E))
                            + g1 * exp2f(fmaf(C_LOG2E, cacc[1], -C_LOG2E));
            rs[mi * 2 + 1] += g0 * exp2f(fmaf(C_LOG2E, cacc[2], -C_LOG2E))
                            + g1 * exp2f(fmaf(C_LOG2E, cacc[3], -C_LOG2E));
        }
    }
    #pragma unroll
    for (int i = 0; i < 4; i++) {
        rs[i] += __shfl_xor_sync(0xffffffffu, rs[i], 1);
        rs[i] += __shfl_xor_sync(0xffffffffu, rs[i], 2);
    }
    if ((lid & 3) == 0) {
        int r0 = m0 + wm * 32 + (lid >> 2);
        atomicAdd(&g_rowsum[r0 +  0], rs[0]);
        atomicAdd(&g_rowsum[r0 +  8], rs[1]);
        atomicAdd(&g_rowsum[r0 + 16], rs[2]);
        atomicAdd(&g_rowsum[r0 + 24], rs[3]);
    }
}

// ---------------- 5: final reduce --------------------------------------------
__global__ void k_final(float* __restrict__ out) {
    int t = threadIdx.x;          // 1024
    float s = 0.0f;
    for (int b = t; b < BB; b += 1024)
        s += (OIM_SCALE + logf(g_rowsum[b])) - g_target[b];
    #pragma unroll
    for (int o = 16; o; o >>= 1) s += __shfl_xor_sync(0xffffffffu, s, o);
    __shared__ float sh[32];
    if ((t & 31) == 0) sh[t >> 5] = s;
    __syncthreads();
    if (t == 0) {
        float tot = 0.0f;
        #pragma unroll
        for (int w = 0; w < 32; w++) tot += sh[w];
        out[0] = tot / (float)BB;
    }
}

// ---------------- launch ------------------------------------------------------
extern "C" void kernel_launch(void* const* d_in, const int* in_sizes, int n_in,
                              void* d_out, int out_size) {
    const float* inputs   = (const float*)d_in[0];
    const int*   labels   = (const int*)  d_in[1];
    const float* emb_cq   = (const float*)d_in[2];
    const int*   label_cq = (const int*)  d_in[3];
    const int*   header   = (const int*)  d_in[5];
    float* out = (float*)d_out;

    cudaFuncSetAttribute(k_gemm, cudaFuncAttributeMaxDynamicSharedMemorySize,
                         SMEM_DYN);

    k_row<<<BB / 2, 128>>>(inputs, labels);
    k_class<<<UU, 128>>>();
    k_build<<<QQ / 2 + BB, 128>>>(emb_cq, label_cq, header, labels, inputs);
    dim3 grid(QQ / 128, BB / 128);
    k_gemm<<<grid, 256, SMEM_DYN>>>();
    k_final<<<1, 1024>>>(out);
}

// round 12
// speedup vs baseline: 1.0592x; 1.0038x over previous
#include <cuda_runtime.h>
#include <cuda_bf16.h>
#include <math.h>
#include <stdint.h>

#define BB 4096
#define DD 512
#define QQ 16384
#define UU 256
#define OIM_SCALE 30.0f
#define C_LOG2E 43.280851226668896f   // 30 * log2(e)

// ---------------- scratch (device globals; no allocation allowed) ----------
__device__ float g_cls_sum[UU * DD];              // zeroed by k_gemm prologue
__device__ int   g_cls_cnt[UU];                   // zeroed by k_gemm prologue
__device__ int   g_unrank[UU];
__device__ float g_uniq_emb_n[UU * DD];
__device__ __nv_bfloat16 g_Abf[BB * DD];          // 4 MB (normalized inputs, bf16)
__device__ __nv_bfloat16 g_Bbf[(size_t)QQ * DD];  // 16 MB (effective queue, bf16)
__device__ unsigned char g_good[QQ];
__device__ float g_target[BB];
__device__ float g_rowsum[BB];

// ---------------- helpers ----------------------------------------------------
__device__ __forceinline__ uint32_t smem_u32(const void* p) {
    uint32_t a;
    asm("{ .reg .u64 t; cvta.to.shared.u64 t, %1; cvt.u32.u64 %0, t; }"
        : "=r"(a) : "l"(p));
    return a;
}
__device__ __forceinline__ void cpa16(uint32_t sm, const void* g) {
    asm volatile("cp.async.cg.shared.global [%0], [%1], 16;" :: "r"(sm), "l"(g));
}
__device__ __forceinline__ void cpa_commit() {
    asm volatile("cp.async.commit_group;" ::: "memory");
}
__device__ __forceinline__ void ldsm4(uint32_t* r, uint32_t addr) {
    asm volatile("ldmatrix.sync.aligned.m8n8.x4.shared.b16 {%0,%1,%2,%3}, [%4];"
                 : "=r"(r[0]), "=r"(r[1]), "=r"(r[2]), "=r"(r[3]) : "r"(addr));
}
__device__ __forceinline__ void mma16816(float* d, const uint32_t* a,
                                         const uint32_t* b) {
    asm volatile(
        "mma.sync.aligned.m16n8k16.row.col.f32.bf16.bf16.f32 "
        "{%0,%1,%2,%3}, {%4,%5,%6,%7}, {%8,%9}, {%0,%1,%2,%3};"
        : "+f"(d[0]), "+f"(d[1]), "+f"(d[2]), "+f"(d[3])
        : "r"(a[0]), "r"(a[1]), "r"(a[2]), "r"(a[3]), "r"(b[0]), "r"(b[1]));
}
#define SWZ(o) ((o) ^ (((o) >> 3) & 0x70))

__device__ __forceinline__ void pack_bf16_store(float4 v, __nv_bfloat16* dst,
                                                size_t e) {
    __nv_bfloat162 h01 = __floats2bfloat162_rn(v.x, v.y);
    __nv_bfloat162 h23 = __floats2bfloat162_rn(v.z, v.w);
    uint2 u;
    u.x = *reinterpret_cast<uint32_t*>(&h01);
    u.y = *reinterpret_cast<uint32_t*>(&h23);
    reinterpret_cast<uint2*>(dst)[e >> 2] = u;
}

// ---------------- 1: normalize rows -> bf16 A + scatter (4 rows/block) ------
__global__ void k_row(const float* __restrict__ inputs,
                      const int*   __restrict__ labels) {
    int b0 = blockIdx.x * 4;      // 1024 blocks
    int t = threadIdx.x;          // 128
    float4 v[4];
    #pragma unroll
    for (int i = 0; i < 4; i++)
        v[i] = reinterpret_cast<const float4*>(inputs + (size_t)(b0 + i) * DD)[t];
    float s[4];
    #pragma unroll
    for (int i = 0; i < 4; i++)
        s[i] = v[i].x * v[i].x + v[i].y * v[i].y + v[i].z * v[i].z + v[i].w * v[i].w;
    #pragma unroll
    for (int o = 16; o; o >>= 1)
        #pragma unroll
        for (int i = 0; i < 4; i++)
            s[i] += __shfl_xor_sync(0xffffffffu, s[i], o);
    __shared__ float sh[4][4];
    if ((t & 31) == 0)
        #pragma unroll
        for (int i = 0; i < 4; i++) sh[i][t >> 5] = s[i];
    __syncthreads();
    #pragma unroll
    for (int i = 0; i < 4; i++) {
        float inv = 1.0f / fmaxf(sqrtf(sh[i][0] + sh[i][1] + sh[i][2] + sh[i][3]), 1e-12f);
        pack_bf16_store(make_float4(v[i].x * inv, v[i].y * inv, v[i].z * inv, v[i].w * inv),
                        g_Abf, (size_t)(b0 + i) * DD + t * 4);
    }
    #pragma unroll
    for (int i = 0; i < 4; i++) {
        int lab = labels[b0 + i];
        float* cs = g_cls_sum + lab * DD + t * 4;
        atomicAdd(cs + 0, v[i].x); atomicAdd(cs + 1, v[i].y);
        atomicAdd(cs + 2, v[i].z); atomicAdd(cs + 3, v[i].w);
        if (t == 0) atomicAdd(&g_cls_cnt[lab], 1);
    }
}

// ---------------- 2: class means, normalized + rank table --------------------
__global__ void k_class() {
    int u = blockIdx.x;           // 256 blocks
    int t = threadIdx.x;          // 128
    int cnt = g_cls_cnt[u];
    float invc = cnt > 0 ? 1.0f / (float)cnt : 0.0f;
    float4 v = reinterpret_cast<const float4*>(g_cls_sum + u * DD)[t];
    v.x *= invc; v.y *= invc; v.z *= invc; v.w *= invc;
    float ss = v.x * v.x + v.y * v.y + v.z * v.z + v.w * v.w;
    #pragma unroll
    for (int o = 16; o; o >>= 1) ss += __shfl_xor_sync(0xffffffffu, ss, o);
    __shared__ float sh[4];
    __shared__ int shr[4];
    int rloc = 0;
    if (t < u && g_cls_cnt[t] > 0) rloc++;
    if (t + 128 < u && g_cls_cnt[t + 128] > 0) rloc++;
    #pragma unroll
    for (int o = 16; o; o >>= 1) rloc += __shfl_xor_sync(0xffffffffu, rloc, o);
    if ((t & 31) == 0) { sh[t >> 5] = ss; shr[t >> 5] = rloc; }
    __syncthreads();
    float inv = 1.0f / fmaxf(sqrtf(sh[0] + sh[1] + sh[2] + sh[3]), 1e-12f);
    float4 vn = make_float4(v.x * inv, v.y * inv, v.z * inv, v.w * inv);
    reinterpret_cast<float4*>(g_uniq_emb_n + u * DD)[t] = vn;
    if (t == 0 && cnt > 0) {
        int r = shr[0] + shr[1] + shr[2] + shr[3];
        g_unrank[r] = u;
    }
}

// ---------------- 3: fused queue resolution (4 rows, MLP 4) + target logits --
__global__ void k_build(const float* __restrict__ emb_cq,
                        const int*   __restrict__ label_cq,
                        const int*   __restrict__ header,
                        const int*   __restrict__ labels,
                        const float* __restrict__ inputs) {
    int blk = blockIdx.x;
    int t = threadIdx.x;          // 128

    if (blk < QQ / 4) {
        int h0 = header[0];
        int q0 = blk * 4;
        const float* src[4];
        unsigned char good[4];
        #pragma unroll
        for (int i = 0; i < 4; i++) {
            int q = q0 + i;
            int u = q - h0;
            u = ((u % QQ) + QQ) % QQ;
            if (u < UU) {
                src[i] = g_uniq_emb_n + g_unrank[u] * DD;
                good[i] = 1;
            } else {
                int lab = label_cq[q];
                bool inuniq = (lab >= 0 && lab < UU && g_cls_cnt[lab] > 0);
                good[i] = (lab != -1 && !inuniq) ? 1 : 0;
                src[i] = emb_cq + (size_t)q * DD;
            }
        }
        float4 v[4];
        #pragma unroll
        for (int i = 0; i < 4; i++)
            v[i] = reinterpret_cast<const float4*>(src[i])[t];
        #pragma unroll
        for (int i = 0; i < 4; i++)
            pack_bf16_store(v[i], g_Bbf, (size_t)(q0 + i) * DD + t * 4);
        if (t < 4) g_good[q0 + t] = good[t];
    } else {
        int b = blk - QQ / 4;
        int lab = labels[b];
        float4 a = reinterpret_cast<const float4*>(inputs + (size_t)b * DD)[t];
        float4 e = reinterpret_cast<const float4*>(g_uniq_emb_n + lab * DD)[t];
        float ss = a.x * a.x + a.y * a.y + a.z * a.z + a.w * a.w;
        float s  = a.x * e.x + a.y * e.y + a.z * e.z + a.w * e.w;
        #pragma unroll
        for (int o = 16; o; o >>= 1) {
            ss += __shfl_xor_sync(0xffffffffu, ss, o);
            s  += __shfl_xor_sync(0xffffffffu, s, o);
        }
        __shared__ float shs[4], shd[4];
        if ((t & 31) == 0) { shs[t >> 5] = ss; shd[t >> 5] = s; }
        __syncthreads();
        if (t == 0) {
            float tot_ss = shs[0] + shs[1] + shs[2] + shs[3];
            float tot_s  = shd[0] + shd[1] + shd[2] + shd[3];
            float inv = 1.0f / fmaxf(sqrtf(tot_ss), 1e-12f);
            g_target[b] = OIM_SCALE * tot_s * inv;
            g_rowsum[b] = 0.0f;
        }
    }
}

// ---------------- 4: HMMA GEMM + fused masked exp row-sum --------------------
// R9 config with SINGLE barrier per K-chunk (CUTLASS-multistage style).
// Full unroll keeps every SMEM address static (the R4 failure was dynamic
// stage indexing, not the barrier count). Loads at iter c write stage
// (c+2)%3, last consumed at iter c-1; the leading __syncthreads of iter c
// is a block-level shared-memory fence ordering those reads before writes.
#define STAGES 3
#define STAGE_BYTES 32768           // (128+128) rows * 128B
#define B_OFF 16384
#define GOOD_OFF (STAGES * STAGE_BYTES)
#define SMEM_DYN (GOOD_OFF + 512 + 1024)

__global__ void __launch_bounds__(256, 2) k_gemm() {
    extern __shared__ char smraw[];
    const uint32_t sb0 = smem_u32(smraw);
    const uint32_t sbase = (sb0 + 1023) & ~1023u;
    char* smc = smraw + (sbase - sb0);
    float* goodf = (float*)(smc + GOOD_OFF);

    const int tid = threadIdx.x;
    const int lid = tid & 31;
    const int w = tid >> 5;
    const int wm = w >> 1;          // 0..3
    const int wn = w & 1;           // 0..1
    const int n0 = blockIdx.x * 128;
    const int m0 = blockIdx.y * 128;

    // self-cleaning: reset class accumulators for the NEXT graph replay.
    if (blockIdx.y == 0) {
        reinterpret_cast<float4*>(g_cls_sum)[blockIdx.x * 256 + tid] =
            make_float4(0.0f, 0.0f, 0.0f, 0.0f);
        if (blockIdx.x == 0) g_cls_cnt[tid] = 0;
    }

    if (tid < 128) goodf[tid] = (float)g_good[n0 + tid];

    const int lrow = tid >> 3;      // 0..31
    const int lch = tid & 7;
    uint32_t soff[4];
    #pragma unroll
    for (int it = 0; it < 4; it++) {
        uint32_t o = (uint32_t)(lrow + it * 32) * 128 + lch * 16;
        soff[it] = SWZ(o);
    }

    float acc[2][8][4];
    #pragma unroll
    for (int i = 0; i < 2; i++)
        #pragma unroll
        for (int j = 0; j < 8; j++)
            #pragma unroll
            for (int k = 0; k < 4; k++) acc[i][j][k] = 0.0f;

    auto load_stage = [&](int s, int kc) {
        uint32_t sa = sbase + s * STAGE_BYTES;
        const __nv_bfloat16* gA = g_Abf + (size_t)(m0 + lrow) * DD + kc * 64 + lch * 8;
        const __nv_bfloat16* gB = g_Bbf + (size_t)(n0 + lrow) * DD + kc * 64 + lch * 8;
        #pragma unroll
        for (int it = 0; it < 4; it++) {
            cpa16(sa + soff[it], gA + (size_t)it * 32 * DD);
            cpa16(sa + B_OFF + soff[it], gB + (size_t)it * 32 * DD);
        }
        cpa_commit();
    };

    load_stage(0, 0);
    load_stage(1, 1);

    const int arow = wm * 32 + (lid & 15);
    const int acolh = lid >> 4;
    const int brow = wn * 64 + ((lid >> 4) << 3) + (lid & 7);
    const int bcolh = (lid >> 3) & 1;

    #pragma unroll
    for (int c = 0; c < 8; c++) {
        if (c < 7) asm volatile("cp.async.wait_group 1;" ::: "memory");
        else       asm volatile("cp.async.wait_group 0;" ::: "memory");
        __syncthreads();
        if (c + 2 < 8) load_stage((c + 2) % STAGES, c + 2);

        uint32_t sa = sbase + (c % STAGES) * STAGE_BYTES;
        uint32_t sb = sa + B_OFF;
        #pragma unroll
        for (int kk = 0; kk < 4; kk++) {
            uint32_t a[2][4];
            #pragma unroll
            for (int mi = 0; mi < 2; mi++) {
                uint32_t o = (uint32_t)(arow + mi * 16) * 128 +
                             (kk * 2 + acolh) * 16;
                ldsm4(a[mi], sa + SWZ(o));
            }
            uint32_t b[8][2];
            #pragma unroll
            for (int nj = 0; nj < 4; nj++) {
                uint32_t q[4];
                uint32_t o = (uint32_t)(brow + nj * 16) * 128 +
                             (kk * 2 + bcolh) * 16;
                ldsm4(q, sb + SWZ(o));
                b[2 * nj][0] = q[0]; b[2 * nj][1] = q[1];
                b[2 * nj + 1][0] = q[2]; b[2 * nj + 1][1] = q[3];
            }
            #pragma unroll
            for (int mi = 0; mi < 2; mi++)
                #pragma unroll
                for (int ni = 0; ni < 8; ni++)
                    mma16816(acc[mi][ni], a[mi], b[ni]);
        }
        // no trailing barrier: next iteration's loads target stage (c+3)%3,
        // consumed at iter c (this one) ... leading barrier of iter c+1 orders.
    }

    // epilogue: masked exp row-sums (exp2 form)
    float rs[4] = {0.0f, 0.0f, 0.0f, 0.0f};
    #pragma unroll
    for (int mi = 0; mi < 2; mi++) {
        #pragma unroll
        for (int ni = 0; ni < 8; ni++) {
            int col = wn * 64 + ni * 8 + ((lid & 3) << 1);
            float g0 = goodf[col], g1 = goodf[col + 1];
            float* cacc = acc[mi][ni];
            rs[mi * 2 + 0] += g0 * exp2f(fmaf(C_LOG2E, cacc[0], -C_LOG2E))
                            + g1 * exp2f(fmaf(C_LOG2E, cacc[1], -C_LOG2E));
            rs[mi * 2 + 1] += g0 * exp2f(fmaf(C_LOG2E, cacc[2], -C_LOG2E))
                            + g1 * exp2f(fmaf(C_LOG2E, cacc[3], -C_LOG2E));
        }
    }
    #pragma unroll
    for (int i = 0; i < 4; i++) {
        rs[i] += __shfl_xor_sync(0xffffffffu, rs[i], 1);
        rs[i] += __shfl_xor_sync(0xffffffffu, rs[i], 2);
    }
    if ((lid & 3) == 0) {
        int r0 = m0 + wm * 32 + (lid >> 2);
        atomicAdd(&g_rowsum[r0 +  0], rs[0]);
        atomicAdd(&g_rowsum[r0 +  8], rs[1]);
        atomicAdd(&g_rowsum[r0 + 16], rs[2]);
        atomicAdd(&g_rowsum[r0 + 24], rs[3]);
    }
}

// ---------------- 5: final reduce --------------------------------------------
__global__ void k_final(float* __restrict__ out) {
    int t = threadIdx.x;          // 1024
    float s = 0.0f;
    for (int b = t; b < BB; b += 1024)
        s += (OIM_SCALE + logf(g_rowsum[b])) - g_target[b];
    #pragma unroll
    for (int o = 16; o; o >>= 1) s += __shfl_xor_sync(0xffffffffu, s, o);
    __shared__ float sh[32];
    if ((t & 31) == 0) sh[t >> 5] = s;
    __syncthreads();
    if (t == 0) {
        float tot = 0.0f;
        #pragma unroll
        for (int w = 0; w < 32; w++) tot += sh[w];
        out[0] = tot / (float)BB;
    }
}

// ---------------- launch ------------------------------------------------------
extern "C" void kernel_launch(void* const* d_in, const int* in_sizes, int n_in,
                              void* d_out, int out_size) {
    const float* inputs   = (const float*)d_in[0];
    const int*   labels   = (const int*)  d_in[1];
    const float* emb_cq   = (const float*)d_in[2];
    const int*   label_cq = (const int*)  d_in[3];
    const int*   header   = (const int*)  d_in[5];
    float* out = (float*)d_out;

    cudaFuncSetAttribute(k_gemm, cudaFuncAttributeMaxDynamicSharedMemorySize,
                         SMEM_DYN);

    k_row<<<BB / 4, 128>>>(inputs, labels);
    k_class<<<UU, 128>>>();
    k_build<<<QQ / 4 + BB, 128>>>(emb_cq, label_cq, header, labels, inputs);
    dim3 grid(QQ / 128, BB / 128);
    k_gemm<<<grid, 256, SMEM_DYN>>>();
    k_final<<<1, 1024>>>(out);
}

// round 13
// speedup vs baseline: 1.0703x; 1.0104x over previous
#include <cuda_runtime.h>
#include <cuda_bf16.h>
#include <math.h>
#include <stdint.h>

#define BB 4096
#define DD 512
#define QQ 16384
#define UU 256
#define OIM_SCALE 30.0f
#define C_LOG2E 43.280851226668896f   // 30 * log2(e)

// ---------------- scratch (device globals; no allocation allowed) ----------
__device__ float g_cls_sum[UU * DD];              // zeroed by k_gemm prologue
__device__ int   g_cls_cnt[UU];                   // zeroed by k_gemm prologue
__device__ int   g_unrank[UU];
__device__ float g_uniq_emb_n[UU * DD];
__device__ __nv_bfloat16 g_Abf[BB * DD];          // 4 MB (normalized inputs, bf16)
__device__ __nv_bfloat16 g_Bbf[(size_t)QQ * DD];  // 16 MB (effective queue, bf16)
__device__ unsigned char g_good[QQ];
__device__ float g_target[BB];
__device__ float g_rowsum[BB];

// ---------------- helpers ----------------------------------------------------
__device__ __forceinline__ uint32_t smem_u32(const void* p) {
    uint32_t a;
    asm("{ .reg .u64 t; cvta.to.shared.u64 t, %1; cvt.u32.u64 %0, t; }"
        : "=r"(a) : "l"(p));
    return a;
}
__device__ __forceinline__ void cpa16(uint32_t sm, const void* g) {
    asm volatile("cp.async.cg.shared.global [%0], [%1], 16;" :: "r"(sm), "l"(g));
}
__device__ __forceinline__ void cpa_commit() {
    asm volatile("cp.async.commit_group;" ::: "memory");
}
__device__ __forceinline__ void ldsm4(uint32_t* r, uint32_t addr) {
    asm volatile("ldmatrix.sync.aligned.m8n8.x4.shared.b16 {%0,%1,%2,%3}, [%4];"
                 : "=r"(r[0]), "=r"(r[1]), "=r"(r[2]), "=r"(r[3]) : "r"(addr));
}
__device__ __forceinline__ void mma16816(float* d, const uint32_t* a,
                                         const uint32_t* b) {
    asm volatile(
        "mma.sync.aligned.m16n8k16.row.col.f32.bf16.bf16.f32 "
        "{%0,%1,%2,%3}, {%4,%5,%6,%7}, {%8,%9}, {%0,%1,%2,%3};"
        : "+f"(d[0]), "+f"(d[1]), "+f"(d[2]), "+f"(d[3])
        : "r"(a[0]), "r"(a[1]), "r"(a[2]), "r"(a[3]), "r"(b[0]), "r"(b[1]));
}
#define SWZ(o) ((o) ^ (((o) >> 3) & 0x70))

__device__ __forceinline__ void pack_bf16_store(float4 v, __nv_bfloat16* dst,
                                                size_t e) {
    __nv_bfloat162 h01 = __floats2bfloat162_rn(v.x, v.y);
    __nv_bfloat162 h23 = __floats2bfloat162_rn(v.z, v.w);
    uint2 u;
    u.x = *reinterpret_cast<uint32_t*>(&h01);
    u.y = *reinterpret_cast<uint32_t*>(&h23);
    reinterpret_cast<uint2*>(dst)[e >> 2] = u;
}

// ---------------- 1: normalize rows -> bf16 A + scatter (8 rows/block) ------
__global__ void k_row(const float* __restrict__ inputs,
                      const int*   __restrict__ labels) {
    int b0 = blockIdx.x * 8;      // 512 blocks
    int t = threadIdx.x;          // 128
    float4 v[8];
    #pragma unroll
    for (int i = 0; i < 8; i++)
        v[i] = reinterpret_cast<const float4*>(inputs + (size_t)(b0 + i) * DD)[t];
    float s[8];
    #pragma unroll
    for (int i = 0; i < 8; i++)
        s[i] = v[i].x * v[i].x + v[i].y * v[i].y + v[i].z * v[i].z + v[i].w * v[i].w;
    #pragma unroll
    for (int o = 16; o; o >>= 1)
        #pragma unroll
        for (int i = 0; i < 8; i++)
            s[i] += __shfl_xor_sync(0xffffffffu, s[i], o);
    __shared__ float sh[8][4];
    if ((t & 31) == 0)
        #pragma unroll
        for (int i = 0; i < 8; i++) sh[i][t >> 5] = s[i];
    __syncthreads();
    #pragma unroll
    for (int i = 0; i < 8; i++) {
        float inv = 1.0f / fmaxf(sqrtf(sh[i][0] + sh[i][1] + sh[i][2] + sh[i][3]), 1e-12f);
        pack_bf16_store(make_float4(v[i].x * inv, v[i].y * inv, v[i].z * inv, v[i].w * inv),
                        g_Abf, (size_t)(b0 + i) * DD + t * 4);
    }
    #pragma unroll
    for (int i = 0; i < 8; i++) {
        int lab = labels[b0 + i];
        float* cs = g_cls_sum + lab * DD + t * 4;
        atomicAdd(cs + 0, v[i].x); atomicAdd(cs + 1, v[i].y);
        atomicAdd(cs + 2, v[i].z); atomicAdd(cs + 3, v[i].w);
        if (t == 0) atomicAdd(&g_cls_cnt[lab], 1);
    }
}

// ---------------- 2: class means, normalized + rank table --------------------
__global__ void k_class() {
    int u = blockIdx.x;           // 256 blocks
    int t = threadIdx.x;          // 128
    int cnt = g_cls_cnt[u];
    float invc = cnt > 0 ? 1.0f / (float)cnt : 0.0f;
    float4 v = reinterpret_cast<const float4*>(g_cls_sum + u * DD)[t];
    v.x *= invc; v.y *= invc; v.z *= invc; v.w *= invc;
    float ss = v.x * v.x + v.y * v.y + v.z * v.z + v.w * v.w;
    #pragma unroll
    for (int o = 16; o; o >>= 1) ss += __shfl_xor_sync(0xffffffffu, ss, o);
    __shared__ float sh[4];
    __shared__ int shr[4];
    int rloc = 0;
    if (t < u && g_cls_cnt[t] > 0) rloc++;
    if (t + 128 < u && g_cls_cnt[t + 128] > 0) rloc++;
    #pragma unroll
    for (int o = 16; o; o >>= 1) rloc += __shfl_xor_sync(0xffffffffu, rloc, o);
    if ((t & 31) == 0) { sh[t >> 5] = ss; shr[t >> 5] = rloc; }
    __syncthreads();
    float inv = 1.0f / fmaxf(sqrtf(sh[0] + sh[1] + sh[2] + sh[3]), 1e-12f);
    float4 vn = make_float4(v.x * inv, v.y * inv, v.z * inv, v.w * inv);
    reinterpret_cast<float4*>(g_uniq_emb_n + u * DD)[t] = vn;
    if (t == 0 && cnt > 0) {
        int r = shr[0] + shr[1] + shr[2] + shr[3];
        g_unrank[r] = u;
    }
}

// ---------------- 3: fused queue resolution (8 rows, MLP 8) + target logits --
__global__ void k_build(const float* __restrict__ emb_cq,
                        const int*   __restrict__ label_cq,
                        const int*   __restrict__ header,
                        const int*   __restrict__ labels,
                        const float* __restrict__ inputs) {
    int blk = blockIdx.x;
    int t = threadIdx.x;          // 128

    if (blk < QQ / 8) {
        int h0 = header[0];
        int q0 = blk * 8;
        const float* src[8];
        uint64_t gpack = 0;
        #pragma unroll
        for (int i = 0; i < 8; i++) {
            int q = q0 + i;
            int u = q - h0;
            u = ((u % QQ) + QQ) % QQ;
            unsigned char good;
            if (u < UU) {
                src[i] = g_uniq_emb_n + g_unrank[u] * DD;
                good = 1;
            } else {
                int lab = label_cq[q];
                bool inuniq = (lab >= 0 && lab < UU && g_cls_cnt[lab] > 0);
                good = (lab != -1 && !inuniq) ? 1 : 0;
                src[i] = emb_cq + (size_t)q * DD;
            }
            gpack |= (uint64_t)good << (8 * i);
        }
        float4 v[8];
        #pragma unroll
        for (int i = 0; i < 8; i++)
            v[i] = reinterpret_cast<const float4*>(src[i])[t];
        #pragma unroll
        for (int i = 0; i < 8; i++)
            pack_bf16_store(v[i], g_Bbf, (size_t)(q0 + i) * DD + t * 4);
        if (t == 0)
            *reinterpret_cast<uint64_t*>(g_good + q0) = gpack;
    } else {
        int b = blk - QQ / 8;
        int lab = labels[b];
        float4 a = reinterpret_cast<const float4*>(inputs + (size_t)b * DD)[t];
        float4 e = reinterpret_cast<const float4*>(g_uniq_emb_n + lab * DD)[t];
        float ss = a.x * a.x + a.y * a.y + a.z * a.z + a.w * a.w;
        float s  = a.x * e.x + a.y * e.y + a.z * e.z + a.w * e.w;
        #pragma unroll
        for (int o = 16; o; o >>= 1) {
            ss += __shfl_xor_sync(0xffffffffu, ss, o);
            s  += __shfl_xor_sync(0xffffffffu, s, o);
        }
        __shared__ float shs[4], shd[4];
        if ((t & 31) == 0) { shs[t >> 5] = ss; shd[t >> 5] = s; }
        __syncthreads();
        if (t == 0) {
            float tot_ss = shs[0] + shs[1] + shs[2] + shs[3];
            float tot_s  = shd[0] + shd[1] + shd[2] + shd[3];
            float inv = 1.0f / fmaxf(sqrtf(tot_ss), 1e-12f);
            g_target[b] = OIM_SCALE * tot_s * inv;
            g_rowsum[b] = 0.0f;
        }
    }
}

// ---------------- 4: HMMA GEMM + fused masked exp row-sum --------------------
// Converged config (R12): 128x128 tile, 3 cp.async stages, 8 warps 4m x 2n,
// full unroll, single barrier per K-chunk, occ 2. DO NOT PERTURB.
#define STAGES 3
#define STAGE_BYTES 32768           // (128+128) rows * 128B
#define B_OFF 16384
#define GOOD_OFF (STAGES * STAGE_BYTES)
#define SMEM_DYN (GOOD_OFF + 512 + 1024)

__global__ void __launch_bounds__(256, 2) k_gemm() {
    extern __shared__ char smraw[];
    const uint32_t sb0 = smem_u32(smraw);
    const uint32_t sbase = (sb0 + 1023) & ~1023u;
    char* smc = smraw + (sbase - sb0);
    float* goodf = (float*)(smc + GOOD_OFF);

    const int tid = threadIdx.x;
    const int lid = tid & 31;
    const int w = tid >> 5;
    const int wm = w >> 1;          // 0..3
    const int wn = w & 1;           // 0..1
    const int n0 = blockIdx.x * 128;
    const int m0 = blockIdx.y * 128;

    // self-cleaning: reset class accumulators for the NEXT graph replay.
    if (blockIdx.y == 0) {
        reinterpret_cast<float4*>(g_cls_sum)[blockIdx.x * 256 + tid] =
            make_float4(0.0f, 0.0f, 0.0f, 0.0f);
        if (blockIdx.x == 0) g_cls_cnt[tid] = 0;
    }

    if (tid < 128) goodf[tid] = (float)g_good[n0 + tid];

    const int lrow = tid >> 3;      // 0..31
    const int lch = tid & 7;
    uint32_t soff[4];
    #pragma unroll
    for (int it = 0; it < 4; it++) {
        uint32_t o = (uint32_t)(lrow + it * 32) * 128 + lch * 16;
        soff[it] = SWZ(o);
    }

    float acc[2][8][4];
    #pragma unroll
    for (int i = 0; i < 2; i++)
        #pragma unroll
        for (int j = 0; j < 8; j++)
            #pragma unroll
            for (int k = 0; k < 4; k++) acc[i][j][k] = 0.0f;

    auto load_stage = [&](int s, int kc) {
        uint32_t sa = sbase + s * STAGE_BYTES;
        const __nv_bfloat16* gA = g_Abf + (size_t)(m0 + lrow) * DD + kc * 64 + lch * 8;
        const __nv_bfloat16* gB = g_Bbf + (size_t)(n0 + lrow) * DD + kc * 64 + lch * 8;
        #pragma unroll
        for (int it = 0; it < 4; it++) {
            cpa16(sa + soff[it], gA + (size_t)it * 32 * DD);
            cpa16(sa + B_OFF + soff[it], gB + (size_t)it * 32 * DD);
        }
        cpa_commit();
    };

    load_stage(0, 0);
    load_stage(1, 1);

    const int arow = wm * 32 + (lid & 15);
    const int acolh = lid >> 4;
    const int brow = wn * 64 + ((lid >> 4) << 3) + (lid & 7);
    const int bcolh = (lid >> 3) & 1;

    #pragma unroll
    for (int c = 0; c < 8; c++) {
        if (c < 7) asm volatile("cp.async.wait_group 1;" ::: "memory");
        else       asm volatile("cp.async.wait_group 0;" ::: "memory");
        __syncthreads();
        if (c + 2 < 8) load_stage((c + 2) % STAGES, c + 2);

        uint32_t sa = sbase + (c % STAGES) * STAGE_BYTES;
        uint32_t sb = sa + B_OFF;
        #pragma unroll
        for (int kk = 0; kk < 4; kk++) {
            uint32_t a[2][4];
            #pragma unroll
            for (int mi = 0; mi < 2; mi++) {
                uint32_t o = (uint32_t)(arow + mi * 16) * 128 +
                             (kk * 2 + acolh) * 16;
                ldsm4(a[mi], sa + SWZ(o));
            }
            uint32_t b[8][2];
            #pragma unroll
            for (int nj = 0; nj < 4; nj++) {
                uint32_t q[4];
                uint32_t o = (uint32_t)(brow + nj * 16) * 128 +
                             (kk * 2 + bcolh) * 16;
                ldsm4(q, sb + SWZ(o));
                b[2 * nj][0] = q[0]; b[2 * nj][1] = q[1];
                b[2 * nj + 1][0] = q[2]; b[2 * nj + 1][1] = q[3];
            }
            #pragma unroll
            for (int mi = 0; mi < 2; mi++)
                #pragma unroll
                for (int ni = 0; ni < 8; ni++)
                    mma16816(acc[mi][ni], a[mi], b[ni]);
        }
    }

    // epilogue: masked exp row-sums (exp2 form)
    float rs[4] = {0.0f, 0.0f, 0.0f, 0.0f};
    #pragma unroll
    for (int mi = 0; mi < 2; mi++) {
        #pragma unroll
        for (int ni = 0; ni < 8; ni++) {
            int col = wn * 64 + ni * 8 + ((lid & 3) << 1);
            float g0 = goodf[col], g1 = goodf[col + 1];
            float* cacc = acc[mi][ni];
            rs[mi * 2 + 0] += g0 * exp2f(fmaf(C_LOG2E, cacc[0], -C_LOG2E))
                            + g1 * exp2f(fmaf(C_LOG2E, cacc[1], -C_LOG2E));
            rs[mi * 2 + 1] += g0 * exp2f(fmaf(C_LOG2E, cacc[2], -C_LOG2E))
                            + g1 * exp2f(fmaf(C_LOG2E, cacc[3], -C_LOG2E));
        }
    }
    #pragma unroll
    for (int i = 0; i < 4; i++) {
        rs[i] += __shfl_xor_sync(0xffffffffu, rs[i], 1);
        rs[i] += __shfl_xor_sync(0xffffffffu, rs[i], 2);
    }
    if ((lid & 3) == 0) {
        int r0 = m0 + wm * 32 + (lid >> 2);
        atomicAdd(&g_rowsum[r0 +  0], rs[0]);
        atomicAdd(&g_rowsum[r0 +  8], rs[1]);
        atomicAdd(&g_rowsum[r0 + 16], rs[2]);
        atomicAdd(&g_rowsum[r0 + 24], rs[3]);
    }
}

// ---------------- 5: final reduce --------------------------------------------
__global__ void k_final(float* __restrict__ out) {
    int t = threadIdx.x;          // 512
    float s = 0.0f;
    #pragma unroll
    for (int i = 0; i < BB / 512; i++) {
        int b = t + i * 512;
        s += (OIM_SCALE + __logf(g_rowsum[b])) - g_target[b];
    }
    #pragma unroll
    for (int o = 16; o; o >>= 1) s += __shfl_xor_sync(0xffffffffu, s, o);
    __shared__ float sh[16];
    if ((t & 31) == 0) sh[t >> 5] = s;
    __syncthreads();
    if (t == 0) {
        float tot = 0.0f;
        #pragma unroll
        for (int w = 0; w < 16; w++) tot += sh[w];
        out[0] = tot / (float)BB;
    }
}

// ---------------- launch ------------------------------------------------------
extern "C" void kernel_launch(void* const* d_in, const int* in_sizes, int n_in,
                              void* d_out, int out_size) {
    const float* inputs   = (const float*)d_in[0];
    const int*   labels   = (const int*)  d_in[1];
    const float* emb_cq   = (const float*)d_in[2];
    const int*   label_cq = (const int*)  d_in[3];
    const int*   header   = (const int*)  d_in[5];
    float* out = (float*)d_out;

    cudaFuncSetAttribute(k_gemm, cudaFuncAttributeMaxDynamicSharedMemorySize,
                         SMEM_DYN);

    k_row<<<BB / 8, 128>>>(inputs, labels);
    k_class<<<UU, 128>>>();
    k_build<<<QQ / 8 + BB, 128>>>(emb_cq, label_cq, header, labels, inputs);
    dim3 grid(QQ / 128, BB / 128);
    k_gemm<<<grid, 256, SMEM_DYN>>>();
    k_final<<<1, 512>>>(out);
}

// round 15
// speedup vs baseline: 1.0846x; 1.0134x over previous
#include <cuda_runtime.h>
#include <cuda_bf16.h>
#include <math.h>
#include <stdint.h>

#define BB 4096
#define DD 512
#define QQ 16384
#define UU 256
#define OIM_SCALE 30.0f
#define C_LOG2E 43.280851226668896f   // 30 * log2(e)

// ---------------- scratch (device globals; no allocation allowed) ----------
__device__ float g_cls_sum[UU * DD];              // zeroed by k_gemm prologue
__device__ int   g_cls_cnt[UU];                   // zeroed by k_gemm prologue
__device__ int   g_unrank[UU];
__device__ float g_uniq_emb_n[UU * DD];
__device__ __nv_bfloat16 g_Abf[BB * DD];          // 4 MB (normalized inputs, bf16)
__device__ __nv_bfloat16 g_Bbf[(size_t)QQ * DD];  // 16 MB (effective queue, bf16)
__device__ unsigned char g_good[QQ];
__device__ float g_target[BB];
__device__ float g_rowsum[BB];

// ---------------- helpers ----------------------------------------------------
__device__ __forceinline__ uint32_t smem_u32(const void* p) {
    uint32_t a;
    asm("{ .reg .u64 t; cvta.to.shared.u64 t, %1; cvt.u32.u64 %0, t; }"
        : "=r"(a) : "l"(p));
    return a;
}
__device__ __forceinline__ void cpa16(uint32_t sm, const void* g) {
    asm volatile("cp.async.cg.shared.global [%0], [%1], 16;" :: "r"(sm), "l"(g));
}
__device__ __forceinline__ void cpa_commit() {
    asm volatile("cp.async.commit_group;" ::: "memory");
}
__device__ __forceinline__ void ldsm4(uint32_t* r, uint32_t addr) {
    asm volatile("ldmatrix.sync.aligned.m8n8.x4.shared.b16 {%0,%1,%2,%3}, [%4];"
                 : "=r"(r[0]), "=r"(r[1]), "=r"(r[2]), "=r"(r[3]) : "r"(addr));
}
__device__ __forceinline__ void mma16816(float* d, const uint32_t* a,
                                         const uint32_t* b) {
    asm volatile(
        "mma.sync.aligned.m16n8k16.row.col.f32.bf16.bf16.f32 "
        "{%0,%1,%2,%3}, {%4,%5,%6,%7}, {%8,%9}, {%0,%1,%2,%3};"
        : "+f"(d[0]), "+f"(d[1]), "+f"(d[2]), "+f"(d[3])
        : "r"(a[0]), "r"(a[1]), "r"(a[2]), "r"(a[3]), "r"(b[0]), "r"(b[1]));
}
#define SWZ(o) ((o) ^ (((o) >> 3) & 0x70))

__device__ __forceinline__ void pack_bf16_store(float4 v, __nv_bfloat16* dst,
                                                size_t e) {
    __nv_bfloat162 h01 = __floats2bfloat162_rn(v.x, v.y);
    __nv_bfloat162 h23 = __floats2bfloat162_rn(v.z, v.w);
    uint2 u;
    u.x = *reinterpret_cast<uint32_t*>(&h01);
    u.y = *reinterpret_cast<uint32_t*>(&h23);
    reinterpret_cast<uint2*>(dst)[e >> 2] = u;
}

// ---------------- 1: normalize rows -> bf16 A + scatter (8 rows/block) ------
__global__ void k_row(const float* __restrict__ inputs,
                      const int*   __restrict__ labels) {
    int b0 = blockIdx.x * 8;      // 512 blocks
    int t = threadIdx.x;          // 128
    float4 v[8];
    #pragma unroll
    for (int i = 0; i < 8; i++)
        v[i] = reinterpret_cast<const float4*>(inputs + (size_t)(b0 + i) * DD)[t];
    float s[8];
    #pragma unroll
    for (int i = 0; i < 8; i++)
        s[i] = v[i].x * v[i].x + v[i].y * v[i].y + v[i].z * v[i].z + v[i].w * v[i].w;
    #pragma unroll
    for (int o = 16; o; o >>= 1)
        #pragma unroll
        for (int i = 0; i < 8; i++)
            s[i] += __shfl_xor_sync(0xffffffffu, s[i], o);
    __shared__ float sh[8][4];
    if ((t & 31) == 0)
        #pragma unroll
        for (int i = 0; i < 8; i++) sh[i][t >> 5] = s[i];
    __syncthreads();
    #pragma unroll
    for (int i = 0; i < 8; i++) {
        float inv = 1.0f / fmaxf(sqrtf(sh[i][0] + sh[i][1] + sh[i][2] + sh[i][3]), 1e-12f);
        pack_bf16_store(make_float4(v[i].x * inv, v[i].y * inv, v[i].z * inv, v[i].w * inv),
                        g_Abf, (size_t)(b0 + i) * DD + t * 4);
    }
    #pragma unroll
    for (int i = 0; i < 8; i++) {
        int lab = labels[b0 + i];
        float* cs = g_cls_sum + lab * DD + t * 4;
        atomicAdd(cs + 0, v[i].x); atomicAdd(cs + 1, v[i].y);
        atomicAdd(cs + 2, v[i].z); atomicAdd(cs + 3, v[i].w);
        if (t == 0) atomicAdd(&g_cls_cnt[lab], 1);
    }
}

// ---------------- 2: class means, normalized + rank table --------------------
__global__ void k_class() {
    int u = blockIdx.x;           // 256 blocks
    int t = threadIdx.x;          // 128
    int cnt = g_cls_cnt[u];
    float invc = cnt > 0 ? 1.0f / (float)cnt : 0.0f;
    float4 v = reinterpret_cast<const float4*>(g_cls_sum + u * DD)[t];
    v.x *= invc; v.y *= invc; v.z *= invc; v.w *= invc;
    float ss = v.x * v.x + v.y * v.y + v.z * v.z + v.w * v.w;
    #pragma unroll
    for (int o = 16; o; o >>= 1) ss += __shfl_xor_sync(0xffffffffu, ss, o);
    __shared__ float sh[4];
    __shared__ int shr[4];
    int rloc = 0;
    if (t < u && g_cls_cnt[t] > 0) rloc++;
    if (t + 128 < u && g_cls_cnt[t + 128] > 0) rloc++;
    #pragma unroll
    for (int o = 16; o; o >>= 1) rloc += __shfl_xor_sync(0xffffffffu, rloc, o);
    if ((t & 31) == 0) { sh[t >> 5] = ss; shr[t >> 5] = rloc; }
    __syncthreads();
    float inv = 1.0f / fmaxf(sqrtf(sh[0] + sh[1] + sh[2] + sh[3]), 1e-12f);
    float4 vn = make_float4(v.x * inv, v.y * inv, v.z * inv, v.w * inv);
    reinterpret_cast<float4*>(g_uniq_emb_n + u * DD)[t] = vn;
    if (t == 0 && cnt > 0) {
        int r = shr[0] + shr[1] + shr[2] + shr[3];
        g_unrank[r] = u;
    }
}

// ---------------- 3: fused queue resolution (8 rows, MLP 8) + target logits --
__global__ void k_build(const float* __restrict__ emb_cq,
                        const int*   __restrict__ label_cq,
                        const int*   __restrict__ header,
                        const int*   __restrict__ labels,
                        const float* __restrict__ inputs) {
    int blk = blockIdx.x;
    int t = threadIdx.x;          // 128

    if (blk < QQ / 8) {
        int h0 = header[0];
        int q0 = blk * 8;
        const float* src[8];
        uint64_t gpack = 0;
        #pragma unroll
        for (int i = 0; i < 8; i++) {
            int q = q0 + i;
            int u = q - h0;
            u = ((u % QQ) + QQ) % QQ;
            unsigned char good;
            if (u < UU) {
                src[i] = g_uniq_emb_n + g_unrank[u] * DD;
                good = 1;
            } else {
                int lab = label_cq[q];
                bool inuniq = (lab >= 0 && lab < UU && g_cls_cnt[lab] > 0);
                good = (lab != -1 && !inuniq) ? 1 : 0;
                src[i] = emb_cq + (size_t)q * DD;
            }
            gpack |= (uint64_t)good << (8 * i);
        }
        float4 v[8];
        #pragma unroll
        for (int i = 0; i < 8; i++)
            v[i] = reinterpret_cast<const float4*>(src[i])[t];
        #pragma unroll
        for (int i = 0; i < 8; i++)
            pack_bf16_store(v[i], g_Bbf, (size_t)(q0 + i) * DD + t * 4);
        if (t == 0)
            *reinterpret_cast<uint64_t*>(g_good + q0) = gpack;
    } else {
        int b = blk - QQ / 8;
        int lab = labels[b];
        float4 a = reinterpret_cast<const float4*>(inputs + (size_t)b * DD)[t];
        float4 e = reinterpret_cast<const float4*>(g_uniq_emb_n + lab * DD)[t];
        float ss = a.x * a.x + a.y * a.y + a.z * a.z + a.w * a.w;
        float s  = a.x * e.x + a.y * e.y + a.z * e.z + a.w * e.w;
        #pragma unroll
        for (int o = 16; o; o >>= 1) {
            ss += __shfl_xor_sync(0xffffffffu, ss, o);
            s  += __shfl_xor_sync(0xffffffffu, s, o);
        }
        __shared__ float shs[4], shd[4];
        if ((t & 31) == 0) { shs[t >> 5] = ss; shd[t >> 5] = s; }
        __syncthreads();
        if (t == 0) {
            float tot_ss = shs[0] + shs[1] + shs[2] + shs[3];
            float tot_s  = shd[0] + shd[1] + shd[2] + shd[3];
            float inv = 1.0f / fmaxf(sqrtf(tot_ss), 1e-12f);
            g_target[b] = OIM_SCALE * tot_s * inv;
            g_rowsum[b] = 0.0f;
        }
    }
}

// ---------------- 4: HMMA GEMM + fused masked exp row-sum --------------------
// EXACT R13 proven mainloop (wait -> sync -> load(c+2) -> compute; single
// barrier per chunk; full unroll; occ 2). The wait MUST precede the barrier:
// cp.async completion is per-thread, and the barrier is what publishes each
// warp's completed copies to the others (R14's NaN). Only change vs R13:
// pipeline-fill loads issued before prologue housekeeping.
#define STAGES 3
#define STAGE_BYTES 32768           // (128+128) rows * 128B
#define B_OFF 16384
#define GOOD_OFF (STAGES * STAGE_BYTES)
#define SMEM_DYN (GOOD_OFF + 512 + 1024)

__global__ void __launch_bounds__(256, 2) k_gemm() {
    extern __shared__ char smraw[];
    const uint32_t sb0 = smem_u32(smraw);
    const uint32_t sbase = (sb0 + 1023) & ~1023u;
    char* smc = smraw + (sbase - sb0);
    float* goodf = (float*)(smc + GOOD_OFF);

    const int tid = threadIdx.x;
    const int lid = tid & 31;
    const int w = tid >> 5;
    const int wm = w >> 1;          // 0..3
    const int wn = w & 1;           // 0..1
    const int n0 = blockIdx.x * 128;
    const int m0 = blockIdx.y * 128;

    const int lrow = tid >> 3;      // 0..31
    const int lch = tid & 7;
    uint32_t soff[4];
    #pragma unroll
    for (int it = 0; it < 4; it++) {
        uint32_t o = (uint32_t)(lrow + it * 32) * 128 + lch * 16;
        soff[it] = SWZ(o);
    }

    auto load_stage = [&](int s, int kc) {
        uint32_t sa = sbase + s * STAGE_BYTES;
        const __nv_bfloat16* gA = g_Abf + (size_t)(m0 + lrow) * DD + kc * 64 + lch * 8;
        const __nv_bfloat16* gB = g_Bbf + (size_t)(n0 + lrow) * DD + kc * 64 + lch * 8;
        #pragma unroll
        for (int it = 0; it < 4; it++) {
            cpa16(sa + soff[it], gA + (size_t)it * 32 * DD);
            cpa16(sa + B_OFF + soff[it], gB + (size_t)it * 32 * DD);
        }
        cpa_commit();
    };

    // pipeline fill first, housekeeping after (copies have no dependence on it)
    load_stage(0, 0);
    load_stage(1, 1);

    // self-cleaning: reset class accumulators for the NEXT graph replay.
    if (blockIdx.y == 0) {
        reinterpret_cast<float4*>(g_cls_sum)[blockIdx.x * 256 + tid] =
            make_float4(0.0f, 0.0f, 0.0f, 0.0f);
        if (blockIdx.x == 0) g_cls_cnt[tid] = 0;
    }
    if (tid < 128) goodf[tid] = (float)g_good[n0 + tid];

    float acc[2][8][4];
    #pragma unroll
    for (int i = 0; i < 2; i++)
        #pragma unroll
        for (int j = 0; j < 8; j++)
            #pragma unroll
            for (int k = 0; k < 4; k++) acc[i][j][k] = 0.0f;

    const int arow = wm * 32 + (lid & 15);
    const int acolh = lid >> 4;
    const int brow = wn * 64 + ((lid >> 4) << 3) + (lid & 7);
    const int bcolh = (lid >> 3) & 1;

    #pragma unroll
    for (int c = 0; c < 8; c++) {
        if (c < 7) asm volatile("cp.async.wait_group 1;" ::: "memory");
        else       asm volatile("cp.async.wait_group 0;" ::: "memory");
        __syncthreads();            // publishes all warps' completed copies
        if (c + 2 < 8) load_stage((c + 2) % STAGES, c + 2);

        uint32_t sa = sbase + (c % STAGES) * STAGE_BYTES;
        uint32_t sb = sa + B_OFF;
        #pragma unroll
        for (int kk = 0; kk < 4; kk++) {
            uint32_t a[2][4];
            #pragma unroll
            for (int mi = 0; mi < 2; mi++) {
                uint32_t o = (uint32_t)(arow + mi * 16) * 128 +
                             (kk * 2 + acolh) * 16;
                ldsm4(a[mi], sa + SWZ(o));
            }
            uint32_t b[8][2];
            #pragma unroll
            for (int nj = 0; nj < 4; nj++) {
                uint32_t q[4];
                uint32_t o = (uint32_t)(brow + nj * 16) * 128 +
                             (kk * 2 + bcolh) * 16;
                ldsm4(q, sb + SWZ(o));
                b[2 * nj][0] = q[0]; b[2 * nj][1] = q[1];
                b[2 * nj + 1][0] = q[2]; b[2 * nj + 1][1] = q[3];
            }
            #pragma unroll
            for (int mi = 0; mi < 2; mi++)
                #pragma unroll
                for (int ni = 0; ni < 8; ni++)
                    mma16816(acc[mi][ni], a[mi], b[ni]);
        }
    }

    // epilogue: masked exp row-sums (exp2 form)
    float rs[4] = {0.0f, 0.0f, 0.0f, 0.0f};
    #pragma unroll
    for (int mi = 0; mi < 2; mi++) {
        #pragma unroll
        for (int ni = 0; ni < 8; ni++) {
            int col = wn * 64 + ni * 8 + ((lid & 3) << 1);
            float g0 = goodf[col], g1 = goodf[col + 1];
            float* cacc = acc[mi][ni];
            rs[mi * 2 + 0] += g0 * exp2f(fmaf(C_LOG2E, cacc[0], -C_LOG2E))
                            + g1 * exp2f(fmaf(C_LOG2E, cacc[1], -C_LOG2E));
            rs[mi * 2 + 1] += g0 * exp2f(fmaf(C_LOG2E, cacc[2], -C_LOG2E))
                            + g1 * exp2f(fmaf(C_LOG2E, cacc[3], -C_LOG2E));
        }
    }
    #pragma unroll
    for (int i = 0; i < 4; i++) {
        rs[i] += __shfl_xor_sync(0xffffffffu, rs[i], 1);
        rs[i] += __shfl_xor_sync(0xffffffffu, rs[i], 2);
    }
    if ((lid & 3) == 0) {
        int r0 = m0 + wm * 32 + (lid >> 2);
        atomicAdd(&g_rowsum[r0 +  0], rs[0]);
        atomicAdd(&g_rowsum[r0 +  8], rs[1]);
        atomicAdd(&g_rowsum[r0 + 16], rs[2]);
        atomicAdd(&g_rowsum[r0 + 24], rs[3]);
    }
}

// ---------------- 5: final reduce --------------------------------------------
__global__ void k_final(float* __restrict__ out) {
    int t = threadIdx.x;          // 512
    float s = 0.0f;
    #pragma unroll
    for (int i = 0; i < BB / 512; i++) {
        int b = t + i * 512;
        s += (OIM_SCALE + __logf(g_rowsum[b])) - g_target[b];
    }
    #pragma unroll
    for (int o = 16; o; o >>= 1) s += __shfl_xor_sync(0xffffffffu, s, o);
    __shared__ float sh[16];
    if ((t & 31) == 0) sh[t >> 5] = s;
    __syncthreads();
    if (t == 0) {
        float tot = 0.0f;
        #pragma unroll
        for (int w = 0; w < 16; w++) tot += sh[w];
        out[0] = tot / (float)BB;
    }
}

// ---------------- launch ------------------------------------------------------
extern "C" void kernel_launch(void* const* d_in, const int* in_sizes, int n_in,
                              void* d_out, int out_size) {
    const float* inputs   = (const float*)d_in[0];
    const int*   labels   = (const int*)  d_in[1];
    const float* emb_cq   = (const float*)d_in[2];
    const int*   label_cq = (const int*)  d_in[3];
    const int*   header   = (const int*)  d_in[5];
    float* out = (float*)d_out;

    cudaFuncSetAttribute(k_gemm, cudaFuncAttributeMaxDynamicSharedMemorySize,
                         SMEM_DYN);

    k_row<<<BB / 8, 128>>>(inputs, labels);
    k_class<<<UU, 128>>>();
    k_build<<<QQ / 8 + BB, 128>>>(emb_cq, label_cq, header, labels, inputs);
    dim3 grid(QQ / 128, BB / 128);
    k_gemm<<<grid, 256, SMEM_DYN>>>();
    k_final<<<1, 512>>>(out);
}